// round 11
// baseline (speedup 1.0000x reference)
#include <cuda_runtime.h>
#include <cuda_fp16.h>
#include <cstdint>

// ---------------- problem constants ----------------
#define CB   64
#define CT   512
#define CD   1024
#define CN   1024
#define S_   16
#define NBLK 32
#define MROWS (CB * CT)    // 32768
#define MST   (CB * NBLK)  // 2048
#define NCTA  128          // persistent grid (one wave)

// ---------------- scratch ----------------
__device__ float   g_xp [(size_t)MROWS * CN];   // Xp fp32 (step addend)
__device__ __half  g_xh [(size_t)MROWS * CN];   // X hi plane
__device__ __half  g_ah [(size_t)MROWS * CN];   // a_t hi plane (phase-Y A-side)
__device__ float   g_s1 [(size_t)MST * CN];     // E states fp32
__device__ __half  g_p1h[(size_t)MST * CN];     // state ping
__device__ __half  g_p2h[(size_t)MST * CN];     // state pong
__device__ __half  g_q2h[(size_t)CN * CN];      // powers B-side hi
__device__ __half  g_q2l[(size_t)CN * CN];      // powers B-side lo
__device__ __half  g_wxh[(size_t)CN * CN];
__device__ __half  g_wah[(size_t)CN * CN], g_wal[(size_t)CN * CN];
__device__ __half  g_wyh[(size_t)CN * CN];
__device__ __half  g_wth[(size_t)CN * CN];      // Waa^T hi
__device__ float g_bd[(size_t)NBLK * CB * CN];
__device__ float g_pA[(size_t)CN * CN];
__device__ float g_pB[(size_t)CN * CN];
__device__ float g_part[(size_t)8 * CB * CN];
__device__ unsigned g_cnt;
__device__ unsigned g_gen;

// =====================================================================
// Portable PTX helpers (sm_80-class only)
// =====================================================================
__device__ __forceinline__ uint32_t smem_u32(const void* p) {
    return (uint32_t)__cvta_generic_to_shared(p);
}
__device__ __forceinline__ void cp16(uint32_t dst, const void* src) {
    asm volatile("cp.async.cg.shared.global [%0], [%1], 16;\n" :: "r"(dst), "l"(src));
}
__device__ __forceinline__ void cp_commit() {
    asm volatile("cp.async.commit_group;\n" ::: "memory");
}
__device__ __forceinline__ void cp_wait0() {
    asm volatile("cp.async.wait_group 0;\n" ::: "memory");
}
__device__ __forceinline__ void cp_wait1() {
    asm volatile("cp.async.wait_group 1;\n" ::: "memory");
}
__device__ __forceinline__ void ldsm4(uint32_t& r0, uint32_t& r1, uint32_t& r2, uint32_t& r3, uint32_t a) {
    asm volatile("ldmatrix.sync.aligned.m8n8.x4.shared.b16 {%0,%1,%2,%3}, [%4];\n"
                 : "=r"(r0), "=r"(r1), "=r"(r2), "=r"(r3) : "r"(a));
}
__device__ __forceinline__ void mma16816(float* d, const uint32_t* a, uint32_t b0, uint32_t b1) {
    asm volatile(
        "mma.sync.aligned.m16n8k16.row.col.f32.f16.f16.f32 "
        "{%0,%1,%2,%3}, {%4,%5,%6,%7}, {%8,%9}, {%0,%1,%2,%3};\n"
        : "+f"(d[0]), "+f"(d[1]), "+f"(d[2]), "+f"(d[3])
        : "r"(a[0]), "r"(a[1]), "r"(a[2]), "r"(a[3]), "r"(b0), "r"(b1));
}

// grid-wide barrier: sense-reversing, deterministic, replay-safe
__device__ __forceinline__ void grid_sync() {
    __syncthreads();
    if (threadIdx.x == 0) {
        __threadfence();
        volatile unsigned* gen = &g_gen;
        unsigned my = *gen;
        unsigned old = atomicAdd(&g_cnt, 1u);
        if (old == (unsigned)(NCTA - 1)) {
            g_cnt = 0u;
            __threadfence();
            *gen = my + 1u;
        } else {
            while (*gen == my) { }
        }
        __threadfence();
    }
    __syncthreads();
}

// smem tile: rows x 32 fp16, padded to 40/row
#define TROW   40
#define TILE_B (128 * TROW * 2)    // 10240 bytes (128-row tile)
#define STAGE1_B (2 * TILE_B)      // mega steps: Ah, Bh (1-term)
#define STAGE2_B (3 * TILE_B)      // powers: Ah, Bh, Bl (2-term)
#define MEGA_SMEM (3 * STAGE2_B)   // 92160

// big-tile phase GEMM: A 256x32 + B 128x32 per stage
#define ATILE_BIG (256 * TROW * 2) // 20480
#define STAGEB_B (ATILE_BIG + TILE_B)  // 30720
#define BIG_SMEM (3 * STAGEB_B)        // 92160

// ================= 1-term 3-stage pipeline (mega steps) =================
__device__ __forceinline__ void stage_load1(
    uint32_t sbase, int buf,
    const __half* __restrict__ Ah, const __half* __restrict__ Bh,
    int row0, int col0, int k0, int tid)
{
    const __half* gp0 = Ah + (size_t)row0 * CN + k0;
    const __half* gp1 = Bh + (size_t)col0 * CN + k0;
    uint32_t base = sbase + buf * STAGE1_B;
#pragma unroll
    for (int u = 0; u < 2; u++) {
        int e = tid + u * 256;
        int r = e >> 2, cu = e & 3;
        uint32_t off = (uint32_t)(r * (TROW * 2) + cu * 16);
        size_t gs = (size_t)r * CN + cu * 8;
        cp16(base + off, gp0 + gs);
        cp16(base + TILE_B + off, gp1 + gs);
    }
}

__device__ __forceinline__ void stage_compute1(
    uint32_t sbase, int buf, int wm, int wn, int lane, float acc[4][4][4])
{
    const uint32_t b0 = sbase + buf * STAGE1_B;
    const uint32_t aH = b0, bH = b0 + TILE_B;
    const int arow = wm * 64 + (lane & 15);
    const int brow = wn * 32 + (lane & 7) + ((lane >> 4) & 1) * 8;
#pragma unroll
    for (int k16 = 0; k16 < 2; k16++) {
        const int akc = k16 * 16 + (lane >> 4) * 8;
        const int bkc = k16 * 16 + ((lane >> 3) & 1) * 8;
        uint32_t af[4][4], bh[2][4];
#pragma unroll
        for (int mi = 0; mi < 4; mi++)
            ldsm4(af[mi][0], af[mi][1], af[mi][2], af[mi][3],
                  aH + (uint32_t)((arow + mi * 16) * (TROW * 2) + akc * 2));
#pragma unroll
        for (int nf = 0; nf < 2; nf++)
            ldsm4(bh[nf][0], bh[nf][1], bh[nf][2], bh[nf][3],
                  bH + (uint32_t)((brow + nf * 16) * (TROW * 2) + bkc * 2));
#pragma unroll
        for (int mi = 0; mi < 4; mi++)
#pragma unroll
            for (int nf = 0; nf < 2; nf++)
#pragma unroll
                for (int sub = 0; sub < 2; sub++)
                    mma16816(acc[mi][nf * 2 + sub], af[mi], bh[nf][sub * 2], bh[nf][sub * 2 + 1]);
    }
}

__device__ __forceinline__ void gemm_core1(
    uint32_t sbase, int tid, int wm, int wn, int lane,
    const __half* Ah, const __half* Bh,
    int row0, int col0, float acc[4][4][4])
{
#pragma unroll
    for (int i = 0; i < 4; i++)
#pragma unroll
        for (int j = 0; j < 4; j++)
#pragma unroll
            for (int r = 0; r < 4; r++) acc[i][j][r] = 0.f;
    stage_load1(sbase, 0, Ah, Bh, row0, col0, 0, tid);
    cp_commit();
    stage_load1(sbase, 1, Ah, Bh, row0, col0, 32, tid);
    cp_commit();
    const int NS = CN / 32;
    for (int s = 0; s < NS; s++) {
        if (s + 1 < NS) cp_wait1(); else cp_wait0();
        __syncthreads();
        if (s + 2 < NS) {
            stage_load1(sbase, (s + 2) % 3, Ah, Bh, row0, col0, (s + 2) * 32, tid);
            cp_commit();
        }
        stage_compute1(sbase, s % 3, wm, wn, lane, acc);
    }
}

// ================= 2-term 3-stage pipeline (powers only) =================
__device__ __forceinline__ void stage_load2(
    uint32_t sbase, int buf,
    const __half* __restrict__ Ah,
    const __half* __restrict__ Bh, const __half* __restrict__ Bl,
    int row0, int col0, int k0, int tid)
{
    const __half* gp0 = Ah + (size_t)row0 * CN + k0;
    const __half* gp1 = Bh + (size_t)col0 * CN + k0;
    const __half* gp2 = Bl + (size_t)col0 * CN + k0;
    uint32_t base = sbase + buf * STAGE2_B;
#pragma unroll
    for (int u = 0; u < 2; u++) {
        int e = tid + u * 256;
        int r = e >> 2, cu = e & 3;
        uint32_t off = (uint32_t)(r * (TROW * 2) + cu * 16);
        size_t gs = (size_t)r * CN + cu * 8;
        cp16(base + off, gp0 + gs);
        cp16(base + TILE_B + off, gp1 + gs);
        cp16(base + 2 * TILE_B + off, gp2 + gs);
    }
}

__device__ __forceinline__ void stage_compute2(
    uint32_t sbase, int buf, int wm, int wn, int lane, float acc[4][4][4])
{
    const uint32_t b0 = sbase + buf * STAGE2_B;
    const uint32_t aH = b0, bH = b0 + TILE_B, bL = b0 + 2 * TILE_B;
    const int arow = wm * 64 + (lane & 15);
    const int brow = wn * 32 + (lane & 7) + ((lane >> 4) & 1) * 8;
#pragma unroll
    for (int k16 = 0; k16 < 2; k16++) {
        const int akc = k16 * 16 + (lane >> 4) * 8;
        const int bkc = k16 * 16 + ((lane >> 3) & 1) * 8;
        uint32_t af[4][4], bh[2][4], bl[2][4];
#pragma unroll
        for (int mi = 0; mi < 4; mi++)
            ldsm4(af[mi][0], af[mi][1], af[mi][2], af[mi][3],
                  aH + (uint32_t)((arow + mi * 16) * (TROW * 2) + akc * 2));
#pragma unroll
        for (int nf = 0; nf < 2; nf++)
            ldsm4(bh[nf][0], bh[nf][1], bh[nf][2], bh[nf][3],
                  bH + (uint32_t)((brow + nf * 16) * (TROW * 2) + bkc * 2));
#pragma unroll
        for (int nf = 0; nf < 2; nf++)
            ldsm4(bl[nf][0], bl[nf][1], bl[nf][2], bl[nf][3],
                  bL + (uint32_t)((brow + nf * 16) * (TROW * 2) + bkc * 2));
#pragma unroll
        for (int mi = 0; mi < 4; mi++)
#pragma unroll
            for (int nf = 0; nf < 2; nf++)
#pragma unroll
                for (int sub = 0; sub < 2; sub++) {
                    mma16816(acc[mi][nf * 2 + sub], af[mi], bh[nf][sub * 2], bh[nf][sub * 2 + 1]);
                    mma16816(acc[mi][nf * 2 + sub], af[mi], bl[nf][sub * 2], bl[nf][sub * 2 + 1]);
                }
    }
}

__device__ __forceinline__ void gemm_core2(
    uint32_t sbase, int tid, int wm, int wn, int lane,
    const __half* Ah, const __half* Bh, const __half* Bl,
    int row0, int col0, float acc[4][4][4])
{
#pragma unroll
    for (int i = 0; i < 4; i++)
#pragma unroll
        for (int j = 0; j < 4; j++)
#pragma unroll
            for (int r = 0; r < 4; r++) acc[i][j][r] = 0.f;
    stage_load2(sbase, 0, Ah, Bh, Bl, row0, col0, 0, tid);
    cp_commit();
    stage_load2(sbase, 1, Ah, Bh, Bl, row0, col0, 32, tid);
    cp_commit();
    const int NS = CN / 32;
    for (int s = 0; s < NS; s++) {
        if (s + 1 < NS) cp_wait1(); else cp_wait0();
        __syncthreads();
        if (s + 2 < NS) {
            stage_load2(sbase, (s + 2) % 3, Ah, Bh, Bl, row0, col0, (s + 2) * 32, tid);
            cp_commit();
        }
        stage_compute2(sbase, s % 3, wm, wn, lane, acc);
    }
}

// ---------------- step epilogue (sh nullable for dead-store elim) ----------------
__device__ __forceinline__ void step_epi(
    float acc[4][4][4], int row0, int col0, int wm, int wn, int lane,
    const float* __restrict__ xp, int jstep,
    float* __restrict__ f32out,
    __half* __restrict__ sh, __half* __restrict__ oah)
{
#pragma unroll
    for (int mi = 0; mi < 4; mi++) {
        const int rbase = row0 + wm * 64 + mi * 16 + (lane >> 2);
#pragma unroll
        for (int half = 0; half < 2; half++) {
            const int m = rbase + half * 8;
            const int bb = m >> 5, blk = m & 31;
            const size_t xoff = ((size_t)bb * CT + blk * S_ + jstep) * CN;
#pragma unroll
            for (int ni = 0; ni < 4; ni++) {
                const int c = col0 + wn * 32 + ni * 8 + (lane & 3) * 2;
                float2 x = *(const float2*)&xp[xoff + c];
                float v0 = acc[mi][ni][half * 2 + 0] + x.x;
                float v1 = acc[mi][ni][half * 2 + 1] + x.y;
                if (f32out)
                    *(float2*)&f32out[(size_t)m * CN + c] = make_float2(v0, v1);
                if (sh || oah) {
                    __half2 h = __floats2half2_rn(v0, v1);
                    if (sh)  *(__half2*)&sh[(size_t)m * CN + c] = h;
                    if (oah) *(__half2*)&oah[xoff + c] = h;
                }
            }
        }
    }
}

// =====================================================================
// PERSISTENT MEGA KERNEL (unchanged from round 10)
// =====================================================================
__global__ __launch_bounds__(256, 1) void mega_k(
    const float* __restrict__ xp,
    __half* p1h, __half* p2h, __half* q2h, __half* q2l,
    const __half* wah, const __half* wal, const __half* wth,
    float* s1, float* bd, float* pA, float* pB, float* part,
    __half* ah)
{
    extern __shared__ char smem[];
    const uint32_t sbase = smem_u32(smem);
    const int tid = threadIdx.x, lane = tid & 31, w = tid >> 5;
    const int wm = w & 1, wn = w >> 1;
    const int bid = blockIdx.x;
    const int row0 = (bid >> 3) * 128;
    const int col0 = (bid & 7) * 128;

    // ===== init1 =====
    {
        const size_t base = (size_t)bid * 16384;
#pragma unroll
        for (int i = 0; i < 16; i++) {
            const size_t e = base + (size_t)(tid + i * 256) * 4;
            const int r = (int)(e >> 10), n = (int)(e & 1023);
            const int bb = r >> 5, blk = r & 31;
            float4 v = *(const float4*)&xp[((size_t)bb * CT + blk * S_) * CN + n];
            *(__half2*)&p1h[e]     = __floats2half2_rn(v.x, v.y);
            *(__half2*)&p1h[e + 2] = __floats2half2_rn(v.z, v.w);
        }
    }
    grid_sync();

    // ===== pass1: j = 1..15 =====
    for (int j = 1; j < S_; j++) {
        const bool in1 = (j & 1);
        const __half* ih = in1 ? p1h : p2h;
        __half* oh = in1 ? p2h : p1h;
        float acc[4][4][4];
        gemm_core1(sbase, tid, wm, wn, lane, ih, wah, row0, col0, acc);
        if (j == S_ - 1)
            step_epi(acc, row0, col0, wm, wn, lane, xp, j, s1, nullptr, nullptr);
        else
            step_epi(acc, row0, col0, wm, wn, lane, xp, j, nullptr, oh, nullptr);
        grid_sync();
    }

    // ===== powers: 4 levels =====
    {
        for (int lvl = 0; lvl < 4; lvl++) {
            const __half *iah, *ibh, *ibl;
            float* G = (lvl & 1) ? pB : pA;
            if (lvl == 0) { iah = wth; ibh = wah; ibl = wal; }
            else          { iah = p1h; ibh = q2h; ibl = q2l; }
            if (bid < 64) {
                float acc[4][4][4];
                gemm_core2(sbase, tid, wm, wn, lane, iah, ibh, ibl,
                           (bid >> 3) * 128, (bid & 7) * 128, acc);
#pragma unroll
                for (int mi = 0; mi < 4; mi++) {
                    const int rb = (bid >> 3) * 128 + wm * 64 + mi * 16 + (lane >> 2);
#pragma unroll
                    for (int half = 0; half < 2; half++) {
                        const int m = rb + half * 8;
#pragma unroll
                        for (int ni = 0; ni < 4; ni++) {
                            const int c = (bid & 7) * 128 + wn * 32 + ni * 8 + (lane & 3) * 2;
                            *(float2*)&G[(size_t)m * CN + c] =
                                make_float2(acc[mi][ni][half * 2 + 0], acc[mi][ni][half * 2 + 1]);
                        }
                    }
                }
            }
            grid_sync();
            if (lvl < 3) {
                float (*ts)[33] = (float(*)[33])smem;
                for (int t8 = 0; t8 < 8; t8++) {
                    const int tile = bid * 8 + t8;
                    const int tr = tile >> 5, tc = tile & 31;
                    const int x = tid & 31, y8 = tid >> 5;
                    __syncthreads();
#pragma unroll
                    for (int p = 0; p < 4; p++) {
                        const int y = y8 + p * 8;
                        float v = G[(size_t)(tr * 32 + y) * CN + tc * 32 + x];
                        ts[y][x] = v;
                        p1h[(size_t)(tr * 32 + y) * CN + tc * 32 + x] = __float2half_rn(v);
                    }
                    __syncthreads();
#pragma unroll
                    for (int p = 0; p < 4; p++) {
                        const int y = y8 + p * 8;
                        float v = ts[x][y];
                        __half h = __float2half_rn(v);
                        const size_t di = (size_t)(tc * 32 + y) * CN + tr * 32 + x;
                        q2h[di] = h;
                        q2l[di] = __float2half_rn(v - __half2float(h));
                    }
                }
                grid_sync();
            }
        }
    }

    // ===== boundary chain (fp16 HMMA, split-K reduce; k=31 skipped) =====
    {
        {
            const size_t e = (size_t)bid * 512 + tid * 2;
            const int m = (int)(e >> 10), n = (int)(e & 1023);
            *(float2*)&bd[e] = *(const float2*)&s1[((size_t)(m * NBLK + 0)) * CN + n];
        }

        const int nb = bid & 15, kb = bid >> 4;
        __half* Bq = (__half*)smem;
        __half* Pq = (__half*)(smem + 64 * 136 * 2);
        const uint32_t bq_base = sbase;
        const uint32_t pq_base = sbase + 64 * 136 * 2;

        for (int i = 0; i < 32; i++) {
            const int e = tid + i * 256;
            const int n = e & 63, kk = e >> 6;
            Pq[n * 136 + kk] = __float2half_rn(pB[(size_t)(kb * 128 + kk) * CN + nb * 64 + n]);
        }
        grid_sync();

        const int wm2 = w & 1, wn4 = w >> 1;
        const int arow = wm2 * 32 + (lane & 15);
        const int brow = wn4 * 16 + (lane & 7) + ((lane >> 4) & 1) * 8;
        for (int k = 1; k < NBLK - 1; k++) {
            const float* bsrc = bd + (size_t)(k - 1) * CB * CN;
            for (int i = 0; i < 32; i++) {
                const int e = tid + i * 256;
                const int m = e >> 7, kk = e & 127;
                Bq[m * 136 + kk] = __float2half_rn(bsrc[(size_t)m * CN + kb * 128 + kk]);
            }
            __syncthreads();

            float acc2[2][2][4];
#pragma unroll
            for (int i = 0; i < 2; i++)
#pragma unroll
                for (int j2 = 0; j2 < 2; j2++)
#pragma unroll
                    for (int r = 0; r < 4; r++) acc2[i][j2][r] = 0.f;
#pragma unroll
            for (int kk16 = 0; kk16 < 8; kk16++) {
                const int akc = kk16 * 16 + (lane >> 4) * 8;
                const int bkc = kk16 * 16 + ((lane >> 3) & 1) * 8;
                uint32_t af[2][4], bf[4];
#pragma unroll
                for (int mi = 0; mi < 2; mi++)
                    ldsm4(af[mi][0], af[mi][1], af[mi][2], af[mi][3],
                          bq_base + (uint32_t)((arow + mi * 16) * 272 + akc * 2));
                ldsm4(bf[0], bf[1], bf[2], bf[3],
                      pq_base + (uint32_t)(brow * 272 + bkc * 2));
#pragma unroll
                for (int mi = 0; mi < 2; mi++)
#pragma unroll
                    for (int sub = 0; sub < 2; sub++)
                        mma16816(acc2[mi][sub], af[mi], bf[sub * 2], bf[sub * 2 + 1]);
            }
            float* dst = part + (size_t)kb * CB * CN;
#pragma unroll
            for (int mi = 0; mi < 2; mi++) {
                const int r0 = wm2 * 32 + mi * 16 + (lane >> 2);
#pragma unroll
                for (int sub = 0; sub < 2; sub++) {
                    const int c = nb * 64 + wn4 * 16 + sub * 8 + (lane & 3) * 2;
                    *(float2*)&dst[(size_t)r0 * CN + c] =
                        make_float2(acc2[mi][sub][0], acc2[mi][sub][1]);
                    *(float2*)&dst[(size_t)(r0 + 8) * CN + c] =
                        make_float2(acc2[mi][sub][2], acc2[mi][sub][3]);
                }
            }
            grid_sync();
            {
                const size_t e = (size_t)bid * 512 + tid * 2;
                const int m = (int)(e >> 10), n = (int)(e & 1023);
                float2 v = *(const float2*)&s1[((size_t)(m * NBLK + k)) * CN + n];
#pragma unroll
                for (int s = 0; s < 8; s++) {
                    float2 p = *(const float2*)&part[(size_t)s * CB * CN + e];
                    v.x += p.x; v.y += p.y;
                }
                *(float2*)&bd[(size_t)k * CB * CN + e] = v;
            }
            grid_sync();
        }
    }

    // ===== init3 =====
    {
        const size_t base = (size_t)bid * 16384;
#pragma unroll
        for (int i = 0; i < 16; i++) {
            const size_t e = base + (size_t)(tid + i * 256) * 4;
            const int r = (int)(e >> 10), n = (int)(e & 1023);
            const int bb = r >> 5, blk = r & 31;
            float4 v = make_float4(0.f, 0.f, 0.f, 0.f);
            if (blk) v = *(const float4*)&bd[((size_t)(blk - 1) * CB + bb) * CN + n];
            *(__half2*)&p1h[e]     = __floats2half2_rn(v.x, v.y);
            *(__half2*)&p1h[e + 2] = __floats2half2_rn(v.z, v.w);
        }
    }
    grid_sync();

    // ===== pass3: j = 0..15 =====
    for (int j = 0; j < S_; j++) {
        const bool in1 = ((j & 1) == 0);
        const __half* ih = in1 ? p1h : p2h;
        __half* oh = (j == S_ - 1) ? nullptr : (in1 ? p2h : p1h);
        float acc[4][4][4];
        gemm_core1(sbase, tid, wm, wn, lane, ih, wah, row0, col0, acc);
        step_epi(acc, row0, col0, wm, wn, lane, xp, j, nullptr, oh, ah);
        if (j < S_ - 1) grid_sync();
    }
}

// =====================================================================
// BIG-TILE phase GEMM: CTA 256x128, 8 warps 4x2, warp tile 64x64
//   C = A@W^T + bias, 1-term fp16, fp32 out
// =====================================================================
__global__ __launch_bounds__(256, 1) void mma_gemm_big(
    const __half* __restrict__ Ah, const __half* __restrict__ Bh,
    const float* __restrict__ bias, float* __restrict__ out)
{
    extern __shared__ char smem[];
    const uint32_t sbase = smem_u32(smem);
    const int tid = threadIdx.x, lane = tid & 31, w = tid >> 5;
    const int wm = w & 3;     // 0..3 over M=256 (64 each)
    const int wn = w >> 2;    // 0..1 over N=128 (64 each)
    const int row0 = blockIdx.y * 256, col0 = blockIdx.x * 128;

    float acc[4][8][4];  // mi (16-row frags) x n8 (8-col frags) x 4
#pragma unroll
    for (int i = 0; i < 4; i++)
#pragma unroll
        for (int j = 0; j < 8; j++)
#pragma unroll
            for (int r = 0; r < 4; r++) acc[i][j][r] = 0.f;

    // ---- stage loads: A 256x32 (4 cp16/thread), B 128x32 (2 cp16/thread) ----
    auto load_stage = [&](int buf, int k0) {
        const __half* gp0 = Ah + (size_t)row0 * CN + k0;
        const __half* gp1 = Bh + (size_t)col0 * CN + k0;
        uint32_t base = sbase + buf * STAGEB_B;
#pragma unroll
        for (int u = 0; u < 4; u++) {
            int e = tid + u * 256;     // 0..1023
            int r = e >> 2, cu = e & 3;
            cp16(base + (uint32_t)(r * (TROW * 2) + cu * 16),
                 gp0 + (size_t)r * CN + cu * 8);
        }
#pragma unroll
        for (int u = 0; u < 2; u++) {
            int e = tid + u * 256;     // 0..511
            int r = e >> 2, cu = e & 3;
            cp16(base + ATILE_BIG + (uint32_t)(r * (TROW * 2) + cu * 16),
                 gp1 + (size_t)r * CN + cu * 8);
        }
    };

    load_stage(0, 0);
    cp_commit();
    load_stage(1, 32);
    cp_commit();

    const int arow = wm * 64 + (lane & 15);
    const int brow = wn * 64 + (lane & 7) + ((lane >> 4) & 1) * 8;
    const int NS = CN / 32;
    for (int s = 0; s < NS; s++) {
        if (s + 1 < NS) cp_wait1(); else cp_wait0();
        __syncthreads();
        if (s + 2 < NS) {
            load_stage((s + 2) % 3, (s + 2) * 32);
            cp_commit();
        }
        const uint32_t b0 = sbase + (s % 3) * STAGEB_B;
        const uint32_t aH = b0, bH = b0 + ATILE_BIG;
#pragma unroll
        for (int k16 = 0; k16 < 2; k16++) {
            const int akc = k16 * 16 + (lane >> 4) * 8;
            const int bkc = k16 * 16 + ((lane >> 3) & 1) * 8;
            uint32_t bf[4][4];
#pragma unroll
            for (int nf = 0; nf < 4; nf++)
                ldsm4(bf[nf][0], bf[nf][1], bf[nf][2], bf[nf][3],
                      bH + (uint32_t)((brow + nf * 16) * (TROW * 2) + bkc * 2));
#pragma unroll
            for (int mi = 0; mi < 4; mi++) {
                uint32_t af[4];
                ldsm4(af[0], af[1], af[2], af[3],
                      aH + (uint32_t)((arow + mi * 16) * (TROW * 2) + akc * 2));
#pragma unroll
                for (int nf = 0; nf < 4; nf++)
#pragma unroll
                    for (int sub = 0; sub < 2; sub++)
                        mma16816(acc[mi][nf * 2 + sub], af, bf[nf][sub * 2], bf[nf][sub * 2 + 1]);
            }
        }
    }

    // ---- epilogue ----
#pragma unroll
    for (int mi = 0; mi < 4; mi++) {
        const int rbase = row0 + wm * 64 + mi * 16 + (lane >> 2);
#pragma unroll
        for (int half = 0; half < 2; half++) {
            const int m = rbase + half * 8;
#pragma unroll
            for (int ni = 0; ni < 8; ni++) {
                const int c = col0 + wn * 64 + ni * 8 + (lane & 3) * 2;
                float v0 = acc[mi][ni][half * 2 + 0] + bias[c];
                float v1 = acc[mi][ni][half * 2 + 1] + bias[c + 1];
                *(float2*)&out[(size_t)m * CN + c] = make_float2(v0, v1);
            }
        }
    }
}

// =====================================================================
// Fused prep kernel (block-range dispatch)
// =====================================================================
#define PREP_XB ((MROWS * CN) / 1024)   // 32768
#define PREP_WB ((CN * CN) / 1024)      // 1024
__global__ __launch_bounds__(256) void prep_k(
    const float* __restrict__ X, const float* __restrict__ Wax,
    const float* __restrict__ Waa, const float* __restrict__ Wy,
    __half* __restrict__ xh, __half* __restrict__ wxh, __half* __restrict__ wyh,
    __half* __restrict__ wah, __half* __restrict__ wal, __half* __restrict__ wth)
{
    __shared__ float ts[32][33];
    const int b = blockIdx.x;
    if (b < PREP_XB + 3 * PREP_WB) {
        const float* src;
        __half* hi;
        size_t e;
        bool dolo = false;
        if (b < PREP_XB) {
            src = X; hi = xh;
            e = ((size_t)b * 256 + threadIdx.x) * 4;
        } else if (b < PREP_XB + PREP_WB) {
            src = Wax; hi = wxh;
            e = ((size_t)(b - PREP_XB) * 256 + threadIdx.x) * 4;
        } else if (b < PREP_XB + 2 * PREP_WB) {
            src = Wy; hi = wyh;
            e = ((size_t)(b - PREP_XB - PREP_WB) * 256 + threadIdx.x) * 4;
        } else {
            src = Waa; hi = wah; dolo = true;
            e = ((size_t)(b - PREP_XB - 2 * PREP_WB) * 256 + threadIdx.x) * 4;
        }
        float4 v = *(const float4*)&src[e];
        __half h0 = __float2half_rn(v.x), h1 = __float2half_rn(v.y);
        __half h2 = __float2half_rn(v.z), h3 = __float2half_rn(v.w);
        hi[e] = h0; hi[e + 1] = h1; hi[e + 2] = h2; hi[e + 3] = h3;
        if (dolo) {
            wal[e]     = __float2half_rn(v.x - __half2float(h0));
            wal[e + 1] = __float2half_rn(v.y - __half2float(h1));
            wal[e + 2] = __float2half_rn(v.z - __half2float(h2));
            wal[e + 3] = __float2half_rn(v.w - __half2float(h3));
        }
    } else {
        const int tb = b - (PREP_XB + 3 * PREP_WB);
        const int tr = tb >> 5, tc = tb & 31;
        const int x = threadIdx.x & 31, y8 = threadIdx.x >> 5;
#pragma unroll
        for (int p = 0; p < 4; p++) {
            const int y = y8 + p * 8;
            ts[y][x] = Waa[(size_t)(tr * 32 + y) * CN + tc * 32 + x];
        }
        __syncthreads();
#pragma unroll
        for (int p = 0; p < 4; p++) {
            const int y = y8 + p * 8;
            wth[(size_t)(tc * 32 + y) * CN + tr * 32 + x] = __float2half_rn(ts[x][y]);
        }
    }
}

// =====================================================================
// host
// =====================================================================
extern "C" void kernel_launch(void* const* d_in, const int* in_sizes, int n_in,
                              void* d_out, int out_size)
{
    const float* X   = (const float*)d_in[0];
    const float* Wax = (const float*)d_in[1];
    const float* Waa = (const float*)d_in[2];
    const float* ba  = (const float*)d_in[3];
    const float* Wy  = (const float*)d_in[4];
    const float* by  = (const float*)d_in[5];
    float* Y = (float*)d_out;

    void *xpv, *xhv, *ahv, *s1v, *p1hv, *p2hv, *q2hv, *q2lv;
    void *wxhv, *wahv, *walv, *wyhv, *wthv;
    void *bdv, *pAv, *pBv, *partv;
    cudaGetSymbolAddress(&xpv, g_xp);   cudaGetSymbolAddress(&xhv, g_xh);
    cudaGetSymbolAddress(&ahv, g_ah);   cudaGetSymbolAddress(&s1v, g_s1);
    cudaGetSymbolAddress(&p1hv, g_p1h); cudaGetSymbolAddress(&p2hv, g_p2h);
    cudaGetSymbolAddress(&q2hv, g_q2h); cudaGetSymbolAddress(&q2lv, g_q2l);
    cudaGetSymbolAddress(&wxhv, g_wxh);
    cudaGetSymbolAddress(&wahv, g_wah); cudaGetSymbolAddress(&walv, g_wal);
    cudaGetSymbolAddress(&wyhv, g_wyh); cudaGetSymbolAddress(&wthv, g_wth);
    cudaGetSymbolAddress(&bdv, g_bd);   cudaGetSymbolAddress(&pAv, g_pA);
    cudaGetSymbolAddress(&pBv, g_pB);   cudaGetSymbolAddress(&partv, g_part);

    float* xp = (float*)xpv; float* s1 = (float*)s1v;
    float* bd = (float*)bdv; float* pA = (float*)pAv; float* pB = (float*)pBv;
    float* part = (float*)partv;
    __half* xh  = (__half*)xhv;  __half* ah  = (__half*)ahv;
    __half* p1h = (__half*)p1hv; __half* p2h = (__half*)p2hv;
    __half* q2h = (__half*)q2hv; __half* q2l = (__half*)q2lv;
    __half* wxh = (__half*)wxhv;
    __half* wah = (__half*)wahv; __half* wal = (__half*)walv;
    __half* wyh = (__half*)wyhv; __half* wth = (__half*)wthv;

    cudaFuncSetAttribute(mma_gemm_big, cudaFuncAttributeMaxDynamicSharedMemorySize, BIG_SMEM);
    cudaFuncSetAttribute(mega_k,       cudaFuncAttributeMaxDynamicSharedMemorySize, MEGA_SMEM);

    // ---- fused prep ----
    prep_k<<<PREP_XB + 4 * PREP_WB, 256>>>(X, Wax, Waa, Wy, xh, wxh, wyh, wah, wal, wth);

    // ---- Phase A: Xp = X @ Wax^T + ba ----
    mma_gemm_big<<<dim3(CN / 128, MROWS / 256), 256, BIG_SMEM>>>(
        xh, wxh, ba, xp);

    // ---- persistent middle ----
    mega_k<<<NCTA, 256, MEGA_SMEM>>>(
        xp, p1h, p2h, q2h, q2l, wah, wal, wth,
        s1, bd, pA, pB, part, ah);

    // ---- Phase Y: Y = A @ Wy^T + by ----
    mma_gemm_big<<<dim3(CN / 128, MROWS / 256), 256, BIG_SMEM>>>(
        ah, wyh, by, Y);
}

// round 12
// speedup vs baseline: 1.1503x; 1.1503x over previous
#include <cuda_runtime.h>
#include <cuda_fp16.h>
#include <cstdint>

// ---------------- problem constants ----------------
#define CB   64
#define CT   512
#define CD   1024
#define CN   1024
#define S_   16
#define NBLK 32
#define MROWS (CB * CT)    // 32768
#define MST   (CB * NBLK)  // 2048
#define NCTA  128          // persistent grid (one wave)

// ---------------- scratch ----------------
__device__ float   g_xp [(size_t)MROWS * CN];
__device__ __half  g_xh [(size_t)MROWS * CN];
__device__ __half  g_ah [(size_t)MROWS * CN];
__device__ float   g_s1 [(size_t)MST * CN];
__device__ __half  g_p1h[(size_t)MST * CN];
__device__ __half  g_p2h[(size_t)MST * CN];
__device__ __half  g_q2h[(size_t)CN * CN];
__device__ __half  g_q2l[(size_t)CN * CN];
__device__ __half  g_wxh[(size_t)CN * CN];
__device__ __half  g_wah[(size_t)CN * CN], g_wal[(size_t)CN * CN];
__device__ __half  g_wyh[(size_t)CN * CN];
__device__ __half  g_wth[(size_t)CN * CN];
__device__ float g_bd[(size_t)NBLK * CB * CN];
__device__ float g_pA[(size_t)CN * CN];
__device__ float g_pB[(size_t)CN * CN];
__device__ float g_part[(size_t)8 * CB * CN];
__device__ unsigned g_cnt;
__device__ unsigned g_gen;

// =====================================================================
// Portable PTX helpers
// =====================================================================
__device__ __forceinline__ uint32_t smem_u32(const void* p) {
    return (uint32_t)__cvta_generic_to_shared(p);
}
__device__ __forceinline__ void cp16(uint32_t dst, const void* src) {
    asm volatile("cp.async.cg.shared.global [%0], [%1], 16;\n" :: "r"(dst), "l"(src));
}
__device__ __forceinline__ void cp_commit() {
    asm volatile("cp.async.commit_group;\n" ::: "memory");
}
__device__ __forceinline__ void cp_wait0() {
    asm volatile("cp.async.wait_group 0;\n" ::: "memory");
}
__device__ __forceinline__ void cp_wait1() {
    asm volatile("cp.async.wait_group 1;\n" ::: "memory");
}
__device__ __forceinline__ void ldsm4(uint32_t& r0, uint32_t& r1, uint32_t& r2, uint32_t& r3, uint32_t a) {
    asm volatile("ldmatrix.sync.aligned.m8n8.x4.shared.b16 {%0,%1,%2,%3}, [%4];\n"
                 : "=r"(r0), "=r"(r1), "=r"(r2), "=r"(r3) : "r"(a));
}
__device__ __forceinline__ void mma16816(float* d, const uint32_t* a, uint32_t b0, uint32_t b1) {
    asm volatile(
        "mma.sync.aligned.m16n8k16.row.col.f32.f16.f16.f32 "
        "{%0,%1,%2,%3}, {%4,%5,%6,%7}, {%8,%9}, {%0,%1,%2,%3};\n"
        : "+f"(d[0]), "+f"(d[1]), "+f"(d[2]), "+f"(d[3])
        : "r"(a[0]), "r"(a[1]), "r"(a[2]), "r"(a[3]), "r"(b0), "r"(b1));
}

// grid-wide barrier
__device__ __forceinline__ void grid_sync() {
    __syncthreads();
    if (threadIdx.x == 0) {
        __threadfence();
        volatile unsigned* gen = &g_gen;
        unsigned my = *gen;
        unsigned old = atomicAdd(&g_cnt, 1u);
        if (old == (unsigned)(NCTA - 1)) {
            g_cnt = 0u;
            __threadfence();
            *gen = my + 1u;
        } else {
            while (*gen == my) { }
        }
        __threadfence();
    }
    __syncthreads();
}

#define TROW   40
#define TILE_B (128 * TROW * 2)    // 10240
#define STAGE1_B (2 * TILE_B)      // Ah, Bh
#define STAGE2_B (3 * TILE_B)      // Ah, Bh, Bl
#define PHASE_SMEM (3 * STAGE1_B)  // 61440 (phase kernel, 256 thr, occ 2)
#define MEGA_SMEM (3 * STAGE2_B)   // 92160 (mega, 512 thr)

// =====================================================================
// MEGA (512 threads, 16 warps, warp grid 4x4, warp tile 32x32)
// =====================================================================
__device__ __forceinline__ void m_load1(
    uint32_t sbase, int buf,
    const __half* __restrict__ Ah, const __half* __restrict__ Bh,
    int row0, int col0, int k0, int tid)
{
    const int r = tid >> 2, cu = tid & 3;
    const uint32_t off = (uint32_t)(r * (TROW * 2) + cu * 16);
    const size_t gs = (size_t)r * CN + cu * 8 + k0;
    uint32_t base = sbase + buf * STAGE1_B;
    cp16(base + off, Ah + (size_t)row0 * CN + gs);
    cp16(base + TILE_B + off, Bh + (size_t)col0 * CN + gs);
}

__device__ __forceinline__ void m_compute1(
    uint32_t sbase, int buf, int wm, int wn, int lane, float acc[2][4][4])
{
    const uint32_t b0 = sbase + buf * STAGE1_B;
    const uint32_t aH = b0, bH = b0 + TILE_B;
    const int arow = wm * 32 + (lane & 15);
    const int brow = wn * 32 + (lane & 7) + ((lane >> 4) & 1) * 8;
#pragma unroll
    for (int k16 = 0; k16 < 2; k16++) {
        const int akc = k16 * 16 + (lane >> 4) * 8;
        const int bkc = k16 * 16 + ((lane >> 3) & 1) * 8;
        uint32_t af[2][4], bh[2][4];
#pragma unroll
        for (int mi = 0; mi < 2; mi++)
            ldsm4(af[mi][0], af[mi][1], af[mi][2], af[mi][3],
                  aH + (uint32_t)((arow + mi * 16) * (TROW * 2) + akc * 2));
#pragma unroll
        for (int nf = 0; nf < 2; nf++)
            ldsm4(bh[nf][0], bh[nf][1], bh[nf][2], bh[nf][3],
                  bH + (uint32_t)((brow + nf * 16) * (TROW * 2) + bkc * 2));
#pragma unroll
        for (int mi = 0; mi < 2; mi++)
#pragma unroll
            for (int nf = 0; nf < 2; nf++)
#pragma unroll
                for (int sub = 0; sub < 2; sub++)
                    mma16816(acc[mi][nf * 2 + sub], af[mi], bh[nf][sub * 2], bh[nf][sub * 2 + 1]);
    }
}

__device__ __forceinline__ void m_core1(
    uint32_t sbase, int tid, int wm, int wn, int lane,
    const __half* Ah, const __half* Bh,
    int row0, int col0, float acc[2][4][4])
{
#pragma unroll
    for (int i = 0; i < 2; i++)
#pragma unroll
        for (int j = 0; j < 4; j++)
#pragma unroll
            for (int r = 0; r < 4; r++) acc[i][j][r] = 0.f;
    m_load1(sbase, 0, Ah, Bh, row0, col0, 0, tid);
    cp_commit();
    m_load1(sbase, 1, Ah, Bh, row0, col0, 32, tid);
    cp_commit();
    const int NS = CN / 32;
    for (int s = 0; s < NS; s++) {
        if (s + 1 < NS) cp_wait1(); else cp_wait0();
        __syncthreads();
        if (s + 2 < NS) {
            m_load1(sbase, (s + 2) % 3, Ah, Bh, row0, col0, (s + 2) * 32, tid);
            cp_commit();
        }
        m_compute1(sbase, s % 3, wm, wn, lane, acc);
    }
}

__device__ __forceinline__ void m_load2(
    uint32_t sbase, int buf,
    const __half* __restrict__ Ah,
    const __half* __restrict__ Bh, const __half* __restrict__ Bl,
    int row0, int col0, int k0, int tid)
{
    const int r = tid >> 2, cu = tid & 3;
    const uint32_t off = (uint32_t)(r * (TROW * 2) + cu * 16);
    const size_t gs = (size_t)r * CN + cu * 8 + k0;
    uint32_t base = sbase + buf * STAGE2_B;
    cp16(base + off, Ah + (size_t)row0 * CN + gs);
    cp16(base + TILE_B + off, Bh + (size_t)col0 * CN + gs);
    cp16(base + 2 * TILE_B + off, Bl + (size_t)col0 * CN + gs);
}

__device__ __forceinline__ void m_compute2(
    uint32_t sbase, int buf, int wm, int wn, int lane, float acc[2][4][4])
{
    const uint32_t b0 = sbase + buf * STAGE2_B;
    const uint32_t aH = b0, bH = b0 + TILE_B, bL = b0 + 2 * TILE_B;
    const int arow = wm * 32 + (lane & 15);
    const int brow = wn * 32 + (lane & 7) + ((lane >> 4) & 1) * 8;
#pragma unroll
    for (int k16 = 0; k16 < 2; k16++) {
        const int akc = k16 * 16 + (lane >> 4) * 8;
        const int bkc = k16 * 16 + ((lane >> 3) & 1) * 8;
        uint32_t af[2][4], bh[2][4], bl[2][4];
#pragma unroll
        for (int mi = 0; mi < 2; mi++)
            ldsm4(af[mi][0], af[mi][1], af[mi][2], af[mi][3],
                  aH + (uint32_t)((arow + mi * 16) * (TROW * 2) + akc * 2));
#pragma unroll
        for (int nf = 0; nf < 2; nf++)
            ldsm4(bh[nf][0], bh[nf][1], bh[nf][2], bh[nf][3],
                  bH + (uint32_t)((brow + nf * 16) * (TROW * 2) + bkc * 2));
#pragma unroll
        for (int nf = 0; nf < 2; nf++)
            ldsm4(bl[nf][0], bl[nf][1], bl[nf][2], bl[nf][3],
                  bL + (uint32_t)((brow + nf * 16) * (TROW * 2) + bkc * 2));
#pragma unroll
        for (int mi = 0; mi < 2; mi++)
#pragma unroll
            for (int nf = 0; nf < 2; nf++)
#pragma unroll
                for (int sub = 0; sub < 2; sub++) {
                    mma16816(acc[mi][nf * 2 + sub], af[mi], bh[nf][sub * 2], bh[nf][sub * 2 + 1]);
                    mma16816(acc[mi][nf * 2 + sub], af[mi], bl[nf][sub * 2], bl[nf][sub * 2 + 1]);
                }
    }
}

__device__ __forceinline__ void m_core2(
    uint32_t sbase, int tid, int wm, int wn, int lane,
    const __half* Ah, const __half* Bh, const __half* Bl,
    int row0, int col0, float acc[2][4][4])
{
#pragma unroll
    for (int i = 0; i < 2; i++)
#pragma unroll
        for (int j = 0; j < 4; j++)
#pragma unroll
            for (int r = 0; r < 4; r++) acc[i][j][r] = 0.f;
    m_load2(sbase, 0, Ah, Bh, Bl, row0, col0, 0, tid);
    cp_commit();
    m_load2(sbase, 1, Ah, Bh, Bl, row0, col0, 32, tid);
    cp_commit();
    const int NS = CN / 32;
    for (int s = 0; s < NS; s++) {
        if (s + 1 < NS) cp_wait1(); else cp_wait0();
        __syncthreads();
        if (s + 2 < NS) {
            m_load2(sbase, (s + 2) % 3, Ah, Bh, Bl, row0, col0, (s + 2) * 32, tid);
            cp_commit();
        }
        m_compute2(sbase, s % 3, wm, wn, lane, acc);
    }
}

// step epilogue (512-thread mapping, warp tile 32x32)
__device__ __forceinline__ void m_step_epi(
    float acc[2][4][4], int row0, int col0, int wm, int wn, int lane,
    const float* __restrict__ xp, int jstep,
    float* __restrict__ f32out,
    __half* __restrict__ sh, __half* __restrict__ oah)
{
#pragma unroll
    for (int mi = 0; mi < 2; mi++) {
        const int rbase = row0 + wm * 32 + mi * 16 + (lane >> 2);
#pragma unroll
        for (int half = 0; half < 2; half++) {
            const int m = rbase + half * 8;
            const int bb = m >> 5, blk = m & 31;
            const size_t xoff = ((size_t)bb * CT + blk * S_ + jstep) * CN;
#pragma unroll
            for (int ni = 0; ni < 4; ni++) {
                const int c = col0 + wn * 32 + ni * 8 + (lane & 3) * 2;
                float2 x = *(const float2*)&xp[xoff + c];
                float v0 = acc[mi][ni][half * 2 + 0] + x.x;
                float v1 = acc[mi][ni][half * 2 + 1] + x.y;
                if (f32out)
                    *(float2*)&f32out[(size_t)m * CN + c] = make_float2(v0, v1);
                if (sh || oah) {
                    __half2 h = __floats2half2_rn(v0, v1);
                    if (sh)  *(__half2*)&sh[(size_t)m * CN + c] = h;
                    if (oah) *(__half2*)&oah[xoff + c] = h;
                }
            }
        }
    }
}

__global__ __launch_bounds__(512, 1) void mega_k(
    const float* __restrict__ xp,
    __half* p1h, __half* p2h, __half* q2h, __half* q2l,
    const __half* wah, const __half* wal, const __half* wth,
    float* s1, float* bd, float* pA, float* pB, float* part,
    __half* ah)
{
    extern __shared__ char smem[];
    const uint32_t sbase = smem_u32(smem);
    const int tid = threadIdx.x, lane = tid & 31, w = tid >> 5;  // w 0..15
    const int wm = w & 3, wn = w >> 2;                            // 4x4
    const int bid = blockIdx.x;
    const int row0 = (bid >> 3) * 128;
    const int col0 = (bid & 7) * 128;

    // ===== init1: p1h <- fp16(Xp[t=blk*16]) =====
    {
        const size_t base = (size_t)bid * 16384;
#pragma unroll
        for (int i = 0; i < 8; i++) {
            const size_t e = base + (size_t)(tid + i * 512) * 4;
            const int r = (int)(e >> 10), n = (int)(e & 1023);
            const int bb = r >> 5, blk = r & 31;
            float4 v = *(const float4*)&xp[((size_t)bb * CT + blk * S_) * CN + n];
            *(__half2*)&p1h[e]     = __floats2half2_rn(v.x, v.y);
            *(__half2*)&p1h[e + 2] = __floats2half2_rn(v.z, v.w);
        }
    }
    grid_sync();

    // ===== pass1: j = 1..15 =====
    for (int j = 1; j < S_; j++) {
        const bool in1 = (j & 1);
        const __half* ih = in1 ? p1h : p2h;
        __half* oh = in1 ? p2h : p1h;
        float acc[2][4][4];
        m_core1(sbase, tid, wm, wn, lane, ih, wah, row0, col0, acc);
        if (j == S_ - 1)
            m_step_epi(acc, row0, col0, wm, wn, lane, xp, j, s1, nullptr, nullptr);
        else
            m_step_epi(acc, row0, col0, wm, wn, lane, xp, j, nullptr, oh, nullptr);
        grid_sync();
    }

    // ===== powers: 4 levels (2-term B-side) =====
    {
        for (int lvl = 0; lvl < 4; lvl++) {
            const __half *iah, *ibh, *ibl;
            float* G = (lvl & 1) ? pB : pA;
            if (lvl == 0) { iah = wth; ibh = wah; ibl = wal; }
            else          { iah = p1h; ibh = q2h; ibl = q2l; }
            if (bid < 64) {
                float acc[2][4][4];
                m_core2(sbase, tid, wm, wn, lane, iah, ibh, ibl,
                        (bid >> 3) * 128, (bid & 7) * 128, acc);
#pragma unroll
                for (int mi = 0; mi < 2; mi++) {
                    const int rb = (bid >> 3) * 128 + wm * 32 + mi * 16 + (lane >> 2);
#pragma unroll
                    for (int half = 0; half < 2; half++) {
                        const int m = rb + half * 8;
#pragma unroll
                        for (int ni = 0; ni < 4; ni++) {
                            const int c = (bid & 7) * 128 + wn * 32 + ni * 8 + (lane & 3) * 2;
                            *(float2*)&G[(size_t)m * CN + c] =
                                make_float2(acc[mi][ni][half * 2 + 0], acc[mi][ni][half * 2 + 1]);
                        }
                    }
                }
            }
            grid_sync();
            if (lvl < 3) {
                float (*ts)[33] = (float(*)[33])smem;
                const int x = tid & 31, y16 = tid >> 5;   // 0..15
                for (int t8 = 0; t8 < 8; t8++) {
                    const int tile = bid * 8 + t8;
                    const int tr = tile >> 5, tc = tile & 31;
                    __syncthreads();
#pragma unroll
                    for (int p = 0; p < 2; p++) {
                        const int y = y16 + p * 16;
                        float v = G[(size_t)(tr * 32 + y) * CN + tc * 32 + x];
                        ts[y][x] = v;
                        p1h[(size_t)(tr * 32 + y) * CN + tc * 32 + x] = __float2half_rn(v);
                    }
                    __syncthreads();
#pragma unroll
                    for (int p = 0; p < 2; p++) {
                        const int y = y16 + p * 16;
                        float v = ts[x][y];
                        __half h = __float2half_rn(v);
                        const size_t di = (size_t)(tc * 32 + y) * CN + tr * 32 + x;
                        q2h[di] = h;
                        q2l[di] = __float2half_rn(v - __half2float(h));
                    }
                }
                grid_sync();
            }
        }
    }
    // pB holds the K-major boundary operator

    // ===== boundary chain (fp16 HMMA, split-K reduce; k=31 skipped) =====
    {
        // b_0 init (1 float/thread)
        {
            const int e = bid * 512 + tid;
            const int m = e >> 10, n = e & 1023;
            bd[e] = s1[((size_t)(m * NBLK + 0)) * CN + n];
        }

        const int nb = bid & 15, kb = bid >> 4;
        __half* Bq = (__half*)smem;
        __half* Pq = (__half*)(smem + 64 * 136 * 2);
        const uint32_t bq_base = sbase;
        const uint32_t pq_base = sbase + 64 * 136 * 2;

        for (int i = 0; i < 16; i++) {
            const int e = tid + i * 512;
            const int n = e & 63, kk = e >> 6;
            Pq[n * 136 + kk] = __float2half_rn(pB[(size_t)(kb * 128 + kk) * CN + nb * 64 + n]);
        }
        grid_sync();

        const int wm2 = w & 3, wn4 = w >> 2;          // 4x4 over 64x64
        const int arow = wm2 * 16 + (lane & 15);
        const int brow = wn4 * 16 + (lane & 7) + ((lane >> 4) & 1) * 8;
        for (int k = 1; k < NBLK - 1; k++) {
            const float* bsrc = bd + (size_t)(k - 1) * CB * CN;
            for (int i = 0; i < 16; i++) {
                const int e = tid + i * 512;
                const int m = e >> 7, kk = e & 127;
                Bq[m * 136 + kk] = __float2half_rn(bsrc[(size_t)m * CN + kb * 128 + kk]);
            }
            __syncthreads();

            float acc2[2][4];
#pragma unroll
            for (int j2 = 0; j2 < 2; j2++)
#pragma unroll
                for (int r = 0; r < 4; r++) acc2[j2][r] = 0.f;
#pragma unroll
            for (int kk16 = 0; kk16 < 8; kk16++) {
                const int akc = kk16 * 16 + (lane >> 4) * 8;
                const int bkc = kk16 * 16 + ((lane >> 3) & 1) * 8;
                uint32_t af[4], bf[4];
                ldsm4(af[0], af[1], af[2], af[3],
                      bq_base + (uint32_t)(arow * 272 + akc * 2));
                ldsm4(bf[0], bf[1], bf[2], bf[3],
                      pq_base + (uint32_t)(brow * 272 + bkc * 2));
#pragma unroll
                for (int sub = 0; sub < 2; sub++)
                    mma16816(acc2[sub], af, bf[sub * 2], bf[sub * 2 + 1]);
            }
            float* dst = part + (size_t)kb * CB * CN;
            {
                const int r0 = wm2 * 16 + (lane >> 2);
#pragma unroll
                for (int sub = 0; sub < 2; sub++) {
                    const int c = nb * 64 + wn4 * 16 + sub * 8 + (lane & 3) * 2;
                    *(float2*)&dst[(size_t)r0 * CN + c] =
                        make_float2(acc2[sub][0], acc2[sub][1]);
                    *(float2*)&dst[(size_t)(r0 + 8) * CN + c] =
                        make_float2(acc2[sub][2], acc2[sub][3]);
                }
            }
            grid_sync();
            // reduce: b_k = e_k + sum_s part[s]
            {
                const int e = bid * 512 + tid;
                const int m = e >> 10, n = e & 1023;
                float v = s1[((size_t)(m * NBLK + k)) * CN + n];
#pragma unroll
                for (int s = 0; s < 8; s++)
                    v += part[(size_t)s * CB * CN + e];
                bd[(size_t)k * CB * CN + e] = v;
            }
            grid_sync();
        }
    }

    // ===== init3: p1h <- fp16(seed) =====
    {
        const size_t base = (size_t)bid * 16384;
#pragma unroll
        for (int i = 0; i < 8; i++) {
            const size_t e = base + (size_t)(tid + i * 512) * 4;
            const int r = (int)(e >> 10), n = (int)(e & 1023);
            const int bb = r >> 5, blk = r & 31;
            float4 v = make_float4(0.f, 0.f, 0.f, 0.f);
            if (blk) v = *(const float4*)&bd[((size_t)(blk - 1) * CB + bb) * CN + n];
            *(__half2*)&p1h[e]     = __floats2half2_rn(v.x, v.y);
            *(__half2*)&p1h[e + 2] = __floats2half2_rn(v.z, v.w);
        }
    }
    grid_sync();

    // ===== pass3: j = 0..15 =====
    for (int j = 0; j < S_; j++) {
        const bool in1 = ((j & 1) == 0);
        const __half* ih = in1 ? p1h : p2h;
        __half* oh = (j == S_ - 1) ? nullptr : (in1 ? p2h : p1h);
        float acc[2][4][4];
        m_core1(sbase, tid, wm, wn, lane, ih, wah, row0, col0, acc);
        m_step_epi(acc, row0, col0, wm, wn, lane, xp, j, nullptr, oh, ah);
        if (j < S_ - 1) grid_sync();
    }
}

// =====================================================================
// Phase GEMM (round-10 proven): 256 thr, CTA 128x128, warp tile 64x32, occ 2
// =====================================================================
__device__ __forceinline__ void p_load1(
    uint32_t sbase, int buf,
    const __half* __restrict__ Ah, const __half* __restrict__ Bh,
    int row0, int col0, int k0, int tid)
{
    const __half* gp0 = Ah + (size_t)row0 * CN + k0;
    const __half* gp1 = Bh + (size_t)col0 * CN + k0;
    uint32_t base = sbase + buf * STAGE1_B;
#pragma unroll
    for (int u = 0; u < 2; u++) {
        int e = tid + u * 256;
        int r = e >> 2, cu = e & 3;
        uint32_t off = (uint32_t)(r * (TROW * 2) + cu * 16);
        size_t gs = (size_t)r * CN + cu * 8;
        cp16(base + off, gp0 + gs);
        cp16(base + TILE_B + off, gp1 + gs);
    }
}

__global__ __launch_bounds__(256, 2) void mma_gemm_bias(
    const __half* __restrict__ Ah, const __half* __restrict__ Bh,
    const float* __restrict__ bias, float* __restrict__ out)
{
    extern __shared__ char smem[];
    const uint32_t sbase = smem_u32(smem);
    const int tid = threadIdx.x, lane = tid & 31, w = tid >> 5;
    const int wm = w & 1, wn = w >> 1;
    const int row0 = blockIdx.y * 128, col0 = blockIdx.x * 128;

    float acc[4][4][4];
#pragma unroll
    for (int i = 0; i < 4; i++)
#pragma unroll
        for (int j = 0; j < 4; j++)
#pragma unroll
            for (int r = 0; r < 4; r++) acc[i][j][r] = 0.f;

    p_load1(sbase, 0, Ah, Bh, row0, col0, 0, tid);
    cp_commit();
    p_load1(sbase, 1, Ah, Bh, row0, col0, 32, tid);
    cp_commit();
    const int arow = wm * 64 + (lane & 15);
    const int brow = wn * 32 + (lane & 7) + ((lane >> 4) & 1) * 8;
    const int NS = CN / 32;
    for (int s = 0; s < NS; s++) {
        if (s + 1 < NS) cp_wait1(); else cp_wait0();
        __syncthreads();
        if (s + 2 < NS) {
            p_load1(sbase, (s + 2) % 3, Ah, Bh, row0, col0, (s + 2) * 32, tid);
            cp_commit();
        }
        const uint32_t b0 = sbase + (s % 3) * STAGE1_B;
        const uint32_t aH = b0, bH = b0 + TILE_B;
#pragma unroll
        for (int k16 = 0; k16 < 2; k16++) {
            const int akc = k16 * 16 + (lane >> 4) * 8;
            const int bkc = k16 * 16 + ((lane >> 3) & 1) * 8;
            uint32_t af[4][4], bh[2][4];
#pragma unroll
            for (int mi = 0; mi < 4; mi++)
                ldsm4(af[mi][0], af[mi][1], af[mi][2], af[mi][3],
                      aH + (uint32_t)((arow + mi * 16) * (TROW * 2) + akc * 2));
#pragma unroll
            for (int nf = 0; nf < 2; nf++)
                ldsm4(bh[nf][0], bh[nf][1], bh[nf][2], bh[nf][3],
                      bH + (uint32_t)((brow + nf * 16) * (TROW * 2) + bkc * 2));
#pragma unroll
            for (int mi = 0; mi < 4; mi++)
#pragma unroll
                for (int nf = 0; nf < 2; nf++)
#pragma unroll
                    for (int sub = 0; sub < 2; sub++)
                        mma16816(acc[mi][nf * 2 + sub], af[mi], bh[nf][sub * 2], bh[nf][sub * 2 + 1]);
        }
    }

#pragma unroll
    for (int mi = 0; mi < 4; mi++) {
        const int rbase = row0 + wm * 64 + mi * 16 + (lane >> 2);
#pragma unroll
        for (int half = 0; half < 2; half++) {
            const int m = rbase + half * 8;
#pragma unroll
            for (int ni = 0; ni < 4; ni++) {
                const int c = col0 + wn * 32 + ni * 8 + (lane & 3) * 2;
                float v0 = acc[mi][ni][half * 2 + 0] + bias[c];
                float v1 = acc[mi][ni][half * 2 + 1] + bias[c + 1];
                *(float2*)&out[(size_t)m * CN + c] = make_float2(v0, v1);
            }
        }
    }
}

// =====================================================================
// Fused prep kernel
// =====================================================================
#define PREP_XB ((MROWS * CN) / 1024)   // 32768
#define PREP_WB ((CN * CN) / 1024)      // 1024
__global__ __launch_bounds__(256) void prep_k(
    const float* __restrict__ X, const float* __restrict__ Wax,
    const float* __restrict__ Waa, const float* __restrict__ Wy,
    __half* __restrict__ xh, __half* __restrict__ wxh, __half* __restrict__ wyh,
    __half* __restrict__ wah, __half* __restrict__ wal, __half* __restrict__ wth)
{
    __shared__ float ts[32][33];
    const int b = blockIdx.x;
    if (b < PREP_XB + 3 * PREP_WB) {
        const float* src;
        __half* hi;
        size_t e;
        bool dolo = false;
        if (b < PREP_XB) {
            src = X; hi = xh;
            e = ((size_t)b * 256 + threadIdx.x) * 4;
        } else if (b < PREP_XB + PREP_WB) {
            src = Wax; hi = wxh;
            e = ((size_t)(b - PREP_XB) * 256 + threadIdx.x) * 4;
        } else if (b < PREP_XB + 2 * PREP_WB) {
            src = Wy; hi = wyh;
            e = ((size_t)(b - PREP_XB - PREP_WB) * 256 + threadIdx.x) * 4;
        } else {
            src = Waa; hi = wah; dolo = true;
            e = ((size_t)(b - PREP_XB - 2 * PREP_WB) * 256 + threadIdx.x) * 4;
        }
        float4 v = *(const float4*)&src[e];
        __half h0 = __float2half_rn(v.x), h1 = __float2half_rn(v.y);
        __half h2 = __float2half_rn(v.z), h3 = __float2half_rn(v.w);
        hi[e] = h0; hi[e + 1] = h1; hi[e + 2] = h2; hi[e + 3] = h3;
        if (dolo) {
            wal[e]     = __float2half_rn(v.x - __half2float(h0));
            wal[e + 1] = __float2half_rn(v.y - __half2float(h1));
            wal[e + 2] = __float2half_rn(v.z - __half2float(h2));
            wal[e + 3] = __float2half_rn(v.w - __half2float(h3));
        }
    } else {
        const int tb = b - (PREP_XB + 3 * PREP_WB);
        const int tr = tb >> 5, tc = tb & 31;
        const int x = threadIdx.x & 31, y8 = threadIdx.x >> 5;
#pragma unroll
        for (int p = 0; p < 4; p++) {
            const int y = y8 + p * 8;
            ts[y][x] = Waa[(size_t)(tr * 32 + y) * CN + tc * 32 + x];
        }
        __syncthreads();
#pragma unroll
        for (int p = 0; p < 4; p++) {
            const int y = y8 + p * 8;
            wth[(size_t)(tc * 32 + y) * CN + tr * 32 + x] = __float2half_rn(ts[x][y]);
        }
    }
}

// =====================================================================
// host
// =====================================================================
extern "C" void kernel_launch(void* const* d_in, const int* in_sizes, int n_in,
                              void* d_out, int out_size)
{
    const float* X   = (const float*)d_in[0];
    const float* Wax = (const float*)d_in[1];
    const float* Waa = (const float*)d_in[2];
    const float* ba  = (const float*)d_in[3];
    const float* Wy  = (const float*)d_in[4];
    const float* by  = (const float*)d_in[5];
    float* Y = (float*)d_out;

    void *xpv, *xhv, *ahv, *s1v, *p1hv, *p2hv, *q2hv, *q2lv;
    void *wxhv, *wahv, *walv, *wyhv, *wthv;
    void *bdv, *pAv, *pBv, *partv;
    cudaGetSymbolAddress(&xpv, g_xp);   cudaGetSymbolAddress(&xhv, g_xh);
    cudaGetSymbolAddress(&ahv, g_ah);   cudaGetSymbolAddress(&s1v, g_s1);
    cudaGetSymbolAddress(&p1hv, g_p1h); cudaGetSymbolAddress(&p2hv, g_p2h);
    cudaGetSymbolAddress(&q2hv, g_q2h); cudaGetSymbolAddress(&q2lv, g_q2l);
    cudaGetSymbolAddress(&wxhv, g_wxh);
    cudaGetSymbolAddress(&wahv, g_wah); cudaGetSymbolAddress(&walv, g_wal);
    cudaGetSymbolAddress(&wyhv, g_wyh); cudaGetSymbolAddress(&wthv, g_wth);
    cudaGetSymbolAddress(&bdv, g_bd);   cudaGetSymbolAddress(&pAv, g_pA);
    cudaGetSymbolAddress(&pBv, g_pB);   cudaGetSymbolAddress(&partv, g_part);

    float* xp = (float*)xpv; float* s1 = (float*)s1v;
    float* bd = (float*)bdv; float* pA = (float*)pAv; float* pB = (float*)pBv;
    float* part = (float*)partv;
    __half* xh  = (__half*)xhv;  __half* ah  = (__half*)ahv;
    __half* p1h = (__half*)p1hv; __half* p2h = (__half*)p2hv;
    __half* q2h = (__half*)q2hv; __half* q2l = (__half*)q2lv;
    __half* wxh = (__half*)wxhv;
    __half* wah = (__half*)wahv; __half* wal = (__half*)walv;
    __half* wyh = (__half*)wyhv; __half* wth = (__half*)wthv;

    cudaFuncSetAttribute(mma_gemm_bias, cudaFuncAttributeMaxDynamicSharedMemorySize, PHASE_SMEM);
    cudaFuncSetAttribute(mega_k,        cudaFuncAttributeMaxDynamicSharedMemorySize, MEGA_SMEM);

    // ---- fused prep ----
    prep_k<<<PREP_XB + 4 * PREP_WB, 256>>>(X, Wax, Waa, Wy, xh, wxh, wyh, wah, wal, wth);

    // ---- Phase A: Xp = X @ Wax^T + ba ----
    mma_gemm_bias<<<dim3(CN / 128, MROWS / 128), 256, PHASE_SMEM>>>(
        xh, wxh, ba, xp);

    // ---- persistent middle (512 threads, 16 warps) ----
    mega_k<<<NCTA, 512, MEGA_SMEM>>>(
        xp, p1h, p2h, q2h, q2l, wah, wal, wth,
        s1, bd, pA, pB, part, ah);

    // ---- Phase Y: Y = A @ Wy^T + by ----
    mma_gemm_bias<<<dim3(CN / 128, MROWS / 128), 256, PHASE_SMEM>>>(
        ah, wyh, by, Y);
}